// round 1
// baseline (speedup 1.0000x reference)
#include <cuda_runtime.h>
#include <cstdint>

#define B_WIN 4096
#define NTOK  49
#define CDIM  384
#define NH    12
#define HD    32
#define NWIN  64
#define MTOT  (B_WIN*NTOK)          /* 200704 */
#define QKN   (3*CDIM)              /* 1152 */
#define SCALE 0.17677669529663687f  /* 32^-0.5 */

#define BM 128
#define BN 128
#define BK 32
#define AST 36   /* padded smem stride (floats), 144B: 16B-aligned rows */

/* scratch: [3][B][H][49][32] and [B][49][384] */
__device__ float g_qkv[(size_t)3*B_WIN*NH*NTOK*HD];
__device__ float g_att[(size_t)B_WIN*NTOK*CDIM];

__device__ __forceinline__ uint32_t f2tf32(float x){
    uint32_t r; asm("cvt.rna.tf32.f32 %0, %1;\n" : "=r"(r) : "f"(x)); return r;
}
__device__ __forceinline__ void mma_tf32(float c[4], const uint32_t a[4], const uint32_t b[2]){
    asm volatile(
      "mma.sync.aligned.m16n8k8.row.col.f32.tf32.tf32.f32 "
      "{%0,%1,%2,%3},{%4,%5,%6,%7},{%8,%9},{%0,%1,%2,%3};\n"
      : "+f"(c[0]), "+f"(c[1]), "+f"(c[2]), "+f"(c[3])
      : "r"(a[0]), "r"(a[1]), "r"(a[2]), "r"(a[3]), "r"(b[0]), "r"(b[1]));
}
__device__ __forceinline__ void cp_async16(void* sdst, const void* gsrc){
    uint32_t s = (uint32_t)__cvta_generic_to_shared(sdst);
    asm volatile("cp.async.cg.shared.global [%0], [%1], 16;\n" :: "r"(s), "l"(gsrc));
}

/* ---------------- GEMM: C = A(MxK,row) * B(NxK,row)^T + bias ----------------
   mode 0: A = g_att, write out[m*N+n] (proj)
   mode 1: A = param, scatter q*SCALE,k,v into g_qkv (qkv)                     */
__global__ void __launch_bounds__(256)
gemm_tn_kernel(const float* __restrict__ A, const float* __restrict__ B,
               const float* __restrict__ bias, float* __restrict__ out,
               int N, int K, int mode)
{
    extern __shared__ float smem[];
    float* As = smem;                    /* [2][BM][AST] */
    float* Bs = smem + 2*BM*AST;         /* [2][BN][AST] */

    const int bm = blockIdx.y, bn = blockIdx.x;
    const int tid = threadIdx.x;
    const int warp = tid >> 5, lane = tid & 31;
    const int wm = warp >> 2, wn = warp & 3;     /* 2 x 4 warp grid, warp tile 64x32 */
    const int qt = lane >> 2, qr = lane & 3;

    const float* Ap = (mode == 0) ? g_att : A;

    float acc[4][4][4];
    #pragma unroll
    for (int i=0;i<4;i++)
      #pragma unroll
      for (int j=0;j<4;j++)
        #pragma unroll
        for (int c=0;c<4;c++) acc[i][j][c]=0.f;

    const int nK = K / BK;

    /* ---- tile loader ---- */
    #define LOAD_TILE(buf, ksi) do {                                              \
        int koff = (ksi)*BK;                                                      \
        _Pragma("unroll")                                                         \
        for (int i=0;i<4;i++){                                                    \
            int chunk = tid + 256*i;                                              \
            int row = chunk >> 3; int c4 = (chunk & 7) << 2;                      \
            cp_async16(&As[(buf)*BM*AST + row*AST + c4],                          \
                       Ap + (size_t)(bm*BM + row)*K + koff + c4);                 \
            cp_async16(&Bs[(buf)*BN*AST + row*AST + c4],                          \
                       B  + (size_t)(bn*BN + row)*K + koff + c4);                 \
        }                                                                         \
        asm volatile("cp.async.commit_group;\n" ::);                              \
    } while(0)

    LOAD_TILE(0, 0);

    for (int ks = 0; ks < nK; ks++){
        asm volatile("cp.async.wait_group 0;\n" ::);
        __syncthreads();
        if (ks + 1 < nK) LOAD_TILE((ks+1)&1, ks+1);

        const float* Ab = &As[(ks&1)*BM*AST];
        const float* Bb = &Bs[(ks&1)*BN*AST];

        #pragma unroll
        for (int kk=0; kk<4; kk++){
            const int k0 = kk*8;
            uint32_t afr[4][4], bfr[4][2];
            #pragma unroll
            for (int mt=0; mt<4; mt++){
                int r = wm*64 + mt*16 + qt;
                afr[mt][0] = f2tf32(Ab[ r     *AST + k0 + qr    ]);
                afr[mt][1] = f2tf32(Ab[(r + 8)*AST + k0 + qr    ]);
                afr[mt][2] = f2tf32(Ab[ r     *AST + k0 + qr + 4]);
                afr[mt][3] = f2tf32(Ab[(r + 8)*AST + k0 + qr + 4]);
            }
            #pragma unroll
            for (int nt=0; nt<4; nt++){
                int cN = wn*32 + nt*8 + qt;
                bfr[nt][0] = f2tf32(Bb[cN*AST + k0 + qr    ]);
                bfr[nt][1] = f2tf32(Bb[cN*AST + k0 + qr + 4]);
            }
            #pragma unroll
            for (int mt=0; mt<4; mt++)
                #pragma unroll
                for (int nt=0; nt<4; nt++)
                    mma_tf32(acc[mt][nt], afr[mt], bfr[nt]);
        }
    }
    #undef LOAD_TILE

    /* ---- epilogue ---- */
    if (mode == 1){
        #pragma unroll
        for (int mt=0; mt<4; mt++){
            #pragma unroll
            for (int cc=0; cc<2; cc++){
                int gm  = bm*BM + wm*64 + mt*16 + qt + cc*8;
                int bwi = gm / NTOK;
                int tok = gm - bwi*NTOK;
                #pragma unroll
                for (int nt=0; nt<4; nt++){
                    #pragma unroll
                    for (int p=0; p<2; p++){
                        int gn = bn*BN + wn*32 + nt*8 + 2*qr + p;
                        float v = acc[mt][nt][cc*2 + p] + bias[gn];
                        int which = gn / CDIM;
                        int rest  = gn - which*CDIM;
                        int h = rest >> 5, d = rest & 31;
                        if (which == 0) v *= SCALE;
                        g_qkv[(((size_t)which*B_WIN + bwi)*NH + h)*(NTOK*HD)
                              + tok*HD + d] = v;
                    }
                }
            }
        }
    } else {
        #pragma unroll
        for (int mt=0; mt<4; mt++){
            #pragma unroll
            for (int cc=0; cc<2; cc++){
                int gm = bm*BM + wm*64 + mt*16 + qt + cc*8;
                #pragma unroll
                for (int nt=0; nt<4; nt++){
                    #pragma unroll
                    for (int p=0; p<2; p++){
                        int gn = bn*BN + wn*32 + nt*8 + 2*qr + p;
                        out[(size_t)gm*N + gn] = acc[mt][nt][cc*2 + p] + bias[gn];
                    }
                }
            }
        }
    }
}

/* ---------------- attention: one CTA per (b, h) ---------------- */
__global__ void __launch_bounds__(128)
attn_kernel(const float* __restrict__ mask, const float* __restrict__ rpb)
{
    __shared__ float qs[64*36], ksm[64*36], vsm[64*36], ps[64*68];

    const int b = blockIdx.y, h = blockIdx.x;
    const int tid = threadIdx.x;
    const int warp = tid >> 5, lane = tid & 31;
    const int qt = lane >> 2, qr = lane & 3;

    const size_t base = ((size_t)b*NH + h)*(NTOK*HD);
    const float* qg = g_qkv + base;                                  /* which=0 */
    const float* kg = g_qkv + (size_t)B_WIN*NH*NTOK*HD   + base;     /* which=1 */
    const float* vg = g_qkv + (size_t)2*B_WIN*NH*NTOK*HD + base;     /* which=2 */

    for (int idx = tid; idx < 64*32; idx += 128){
        int r = idx >> 5, c = idx & 31;
        float q = 0.f, k = 0.f, v = 0.f;
        if (r < NTOK){ q = qg[idx]; k = kg[idx]; v = vg[idx]; }
        qs [r*36 + c] = q;
        ksm[r*36 + c] = k;
        vsm[r*36 + c] = v;
    }
    __syncthreads();

    const int r0 = warp*16 + qt;

    /* S = q @ k^T  (64x64, this warp: rows r0, r0+8 over 16-row slab) */
    float S[8][4];
    #pragma unroll
    for (int nt=0; nt<8; nt++)
        #pragma unroll
        for (int c=0; c<4; c++) S[nt][c] = 0.f;

    #pragma unroll
    for (int kk=0; kk<4; kk++){
        uint32_t a[4];
        a[0] = f2tf32(qs[ r0     *36 + kk*8 + qr    ]);
        a[1] = f2tf32(qs[(r0 + 8)*36 + kk*8 + qr    ]);
        a[2] = f2tf32(qs[ r0     *36 + kk*8 + qr + 4]);
        a[3] = f2tf32(qs[(r0 + 8)*36 + kk*8 + qr + 4]);
        #pragma unroll
        for (int nt=0; nt<8; nt++){
            uint32_t bb[2];
            int m = nt*8 + qt;
            bb[0] = f2tf32(ksm[m*36 + kk*8 + qr    ]);
            bb[1] = f2tf32(ksm[m*36 + kk*8 + qr + 4]);
            mma_tf32(S[nt], a, bb);
        }
    }

    /* + rpb + mask, pad cols>=49 with -1e30 */
    const float* mrow = mask + (size_t)(b & (NWIN-1))*NTOK*NTOK;
    #pragma unroll
    for (int nt=0; nt<8; nt++){
        #pragma unroll
        for (int c=0; c<4; c++){
            int row = r0 + ((c >> 1) << 3);
            int m   = nt*8 + 2*qr + (c & 1);
            if (m >= NTOK){
                S[nt][c] = -1e30f;
            } else if (row < NTOK){
                int ri = row / 7, ci = row - ri*7;
                int rj = m   / 7, cj = m   - rj*7;
                int idx = ((ri - rj + 6)*13 + (ci - cj + 6))*NH + h;
                S[nt][c] += rpb[idx] + mrow[row*NTOK + m];
            }
        }
    }

    /* softmax over m (per-row: spread across 4 lanes qr=0..3) */
    float mx[2] = {-1e30f, -1e30f};
    #pragma unroll
    for (int nt=0; nt<8; nt++)
        #pragma unroll
        for (int c=0; c<4; c++){
            int rs = c >> 1;
            mx[rs] = fmaxf(mx[rs], S[nt][c]);
        }
    #pragma unroll
    for (int o=1; o<4; o<<=1){
        mx[0] = fmaxf(mx[0], __shfl_xor_sync(0xffffffffu, mx[0], o));
        mx[1] = fmaxf(mx[1], __shfl_xor_sync(0xffffffffu, mx[1], o));
    }
    float sm[2] = {0.f, 0.f};
    #pragma unroll
    for (int nt=0; nt<8; nt++)
        #pragma unroll
        for (int c=0; c<4; c++){
            int rs = c >> 1;
            S[nt][c] = __expf(S[nt][c] - mx[rs]);
            sm[rs] += S[nt][c];
        }
    #pragma unroll
    for (int o=1; o<4; o<<=1){
        sm[0] += __shfl_xor_sync(0xffffffffu, sm[0], o);
        sm[1] += __shfl_xor_sync(0xffffffffu, sm[1], o);
    }

    /* P -> smem (per-warp region, warp-local reuse) */
    #pragma unroll
    for (int nt=0; nt<8; nt++){
        #pragma unroll
        for (int c=0; c<4; c++){
            int row = r0 + ((c >> 1) << 3);
            int m   = nt*8 + 2*qr + (c & 1);
            ps[row*68 + m] = S[nt][c];
        }
    }
    __syncwarp();

    /* O = P @ v  (16x32 per warp) */
    float O[4][4];
    #pragma unroll
    for (int nt=0; nt<4; nt++)
        #pragma unroll
        for (int c=0; c<4; c++) O[nt][c] = 0.f;

    #pragma unroll
    for (int ksx=0; ksx<8; ksx++){
        uint32_t a[4];
        a[0] = f2tf32(ps[ r0     *68 + ksx*8 + qr    ]);
        a[1] = f2tf32(ps[(r0 + 8)*68 + ksx*8 + qr    ]);
        a[2] = f2tf32(ps[ r0     *68 + ksx*8 + qr + 4]);
        a[3] = f2tf32(ps[(r0 + 8)*68 + ksx*8 + qr + 4]);
        #pragma unroll
        for (int nt=0; nt<4; nt++){
            uint32_t bb[2];
            bb[0] = f2tf32(vsm[(ksx*8 + qr    )*36 + nt*8 + qt]);
            bb[1] = f2tf32(vsm[(ksx*8 + qr + 4)*36 + nt*8 + qt]);
            mma_tf32(O[nt], a, bb);
        }
    }

    const float inv0 = 1.f / sm[0], inv1 = 1.f / sm[1];
    #pragma unroll
    for (int nt=0; nt<4; nt++){
        #pragma unroll
        for (int c=0; c<4; c++){
            int row = r0 + ((c >> 1) << 3);
            if (row < NTOK){
                int d = nt*8 + 2*qr + (c & 1);
                g_att[((size_t)b*NTOK + row)*CDIM + h*HD + d] =
                    O[nt][c] * ((c >> 1) ? inv1 : inv0);
            }
        }
    }
}

extern "C" void kernel_launch(void* const* d_in, const int* in_sizes, int n_in,
                              void* d_out, int out_size)
{
    const float* x      = (const float*)d_in[0];
    const float* mask   = (const float*)d_in[1];
    const float* qkv_w  = (const float*)d_in[2];
    const float* qkv_b  = (const float*)d_in[3];
    const float* proj_w = (const float*)d_in[4];
    const float* proj_b = (const float*)d_in[5];
    const float* rpb    = (const float*)d_in[6];
    float* out = (float*)d_out;

    const size_t smem_bytes = (size_t)2*(BM + BN)*AST*sizeof(float); /* 73728 */
    cudaFuncSetAttribute(gemm_tn_kernel,
                         cudaFuncAttributeMaxDynamicSharedMemorySize,
                         (int)smem_bytes);

    /* K1: qkv = x @ qkv_w^T + b  -> scatter into g_qkv (q pre-scaled) */
    gemm_tn_kernel<<<dim3(QKN/BN, MTOT/BM), 256, smem_bytes>>>(
        x, qkv_w, qkv_b, nullptr, QKN, CDIM, 1);

    /* K2: per-(window, head) attention */
    attn_kernel<<<dim3(NH, B_WIN), 128>>>(mask, rpb);

    /* K3: out = attn_out @ proj_w^T + b */
    gemm_tn_kernel<<<dim3(CDIM/BN, MTOT/BM), 256, smem_bytes>>>(
        nullptr, proj_w, proj_b, out, CDIM, CDIM, 0);
}

// round 2
// speedup vs baseline: 1.1386x; 1.1386x over previous
#include <cuda_runtime.h>
#include <cstdint>

#define B_WIN 4096
#define NTOK  49
#define CDIM  384
#define NH    12
#define HD    32
#define NWIN  64
#define MTOT  (B_WIN*NTOK)          /* 200704 */
#define QKN   (3*CDIM)              /* 1152 */
#define SCALE 0.17677669529663687f  /* 32^-0.5 */

#define BM 128
#define BN 128
#define BK 32
#define AST 36   /* padded smem stride (floats), 144B: 16B-aligned rows */

/* scratch: [3][B][H][49][32] and [B][49][384] */
__device__ float g_qkv[(size_t)3*B_WIN*NH*NTOK*HD];
__device__ float g_att[(size_t)B_WIN*NTOK*CDIM];

__device__ __forceinline__ uint32_t f2tf32(float x){
    uint32_t r; asm("cvt.rna.tf32.f32 %0, %1;\n" : "=r"(r) : "f"(x)); return r;
}
__device__ __forceinline__ void mma_tf32(float c[4], const uint32_t a[4], const uint32_t b[2]){
    asm volatile(
      "mma.sync.aligned.m16n8k8.row.col.f32.tf32.tf32.f32 "
      "{%0,%1,%2,%3},{%4,%5,%6,%7},{%8,%9},{%0,%1,%2,%3};\n"
      : "+f"(c[0]), "+f"(c[1]), "+f"(c[2]), "+f"(c[3])
      : "r"(a[0]), "r"(a[1]), "r"(a[2]), "r"(a[3]), "r"(b[0]), "r"(b[1]));
}
__device__ __forceinline__ void cp_async16(void* sdst, const void* gsrc){
    uint32_t s = (uint32_t)__cvta_generic_to_shared(sdst);
    asm volatile("cp.async.cg.shared.global [%0], [%1], 16;\n" :: "r"(s), "l"(gsrc));
}

/* ---------------- GEMM: C = A(MxK,row) * B(NxK,row)^T + bias ----------------
   MODE 0: A = g_att, write out[m*N+n] (proj)
   MODE 1: A = param, scatter q*SCALE,k,v into g_qkv (qkv)                     */
template<int MODE>
__global__ void __launch_bounds__(256, 2)
gemm_tn_kernel(const float* __restrict__ A, const float* __restrict__ B,
               const float* __restrict__ bias, float* __restrict__ out,
               int N, int K)
{
    extern __shared__ float smem[];
    float* As = smem;                    /* [2][BM][AST] */
    float* Bs = smem + 2*BM*AST;         /* [2][BN][AST] */

    const int bm = blockIdx.y, bn = blockIdx.x;
    const int tid = threadIdx.x;
    const int warp = tid >> 5, lane = tid & 31;
    const int wm = warp >> 2, wn = warp & 3;     /* 2 x 4 warp grid, warp tile 64x32 */
    const int qt = lane >> 2, qr = lane & 3;

    const float* Ap = (MODE == 0) ? g_att : A;

    float acc[4][4][4];
    #pragma unroll
    for (int i=0;i<4;i++)
      #pragma unroll
      for (int j=0;j<4;j++)
        #pragma unroll
        for (int c=0;c<4;c++) acc[i][j][c]=0.f;

    const int nK = K / BK;

    /* ---- tile loader ---- */
    #define LOAD_TILE(buf, ksi) do {                                              \
        int koff = (ksi)*BK;                                                      \
        _Pragma("unroll")                                                         \
        for (int i=0;i<4;i++){                                                    \
            int chunk = tid + 256*i;                                              \
            int row = chunk >> 3; int c4 = (chunk & 7) << 2;                      \
            cp_async16(&As[(buf)*BM*AST + row*AST + c4],                          \
                       Ap + (size_t)(bm*BM + row)*K + koff + c4);                 \
            cp_async16(&Bs[(buf)*BN*AST + row*AST + c4],                          \
                       B  + (size_t)(bn*BN + row)*K + koff + c4);                 \
        }                                                                         \
        asm volatile("cp.async.commit_group;\n" ::);                              \
    } while(0)

    LOAD_TILE(0, 0);

    /* per-warp smem base pointers (hoisted out of the mainloop) */
    const int arow = wm*64;
    const int brow = wn*32;

    for (int ks = 0; ks < nK; ks++){
        asm volatile("cp.async.wait_group 0;\n" ::);
        __syncthreads();
        if (ks + 1 < nK) LOAD_TILE((ks+1)&1, ks+1);

        const float* Ab = &As[(ks&1)*BM*AST + arow*AST + qr];
        const float* Bb = &Bs[(ks&1)*BN*AST + brow*AST + qr];

        #pragma unroll
        for (int kk=0; kk<4; kk++){
            const int k0 = kk*8;
            uint32_t afr[4][4], bfr[4][2];
            #pragma unroll
            for (int mt=0; mt<4; mt++){
                const float* ar = Ab + (mt*16 + qt)*AST + k0;
                afr[mt][0] = f2tf32(ar[0]);
                afr[mt][1] = f2tf32(ar[8*AST]);
                afr[mt][2] = f2tf32(ar[4]);
                afr[mt][3] = f2tf32(ar[8*AST + 4]);
            }
            #pragma unroll
            for (int nt=0; nt<4; nt++){
                const float* br = Bb + (nt*8 + qt)*AST + k0;
                bfr[nt][0] = f2tf32(br[0]);
                bfr[nt][1] = f2tf32(br[4]);
            }
            #pragma unroll
            for (int mt=0; mt<4; mt++)
                #pragma unroll
                for (int nt=0; nt<4; nt++)
                    mma_tf32(acc[mt][nt], afr[mt], bfr[nt]);
        }
    }
    #undef LOAD_TILE

    /* ---- epilogue ---- */
    if (MODE == 1){
        #pragma unroll
        for (int mt=0; mt<4; mt++){
            #pragma unroll
            for (int cc=0; cc<2; cc++){
                int gm  = bm*BM + wm*64 + mt*16 + qt + cc*8;
                int bwi = gm / NTOK;
                int tok = gm - bwi*NTOK;
                #pragma unroll
                for (int nt=0; nt<4; nt++){
                    #pragma unroll
                    for (int p=0; p<2; p++){
                        int gn = bn*BN + wn*32 + nt*8 + 2*qr + p;
                        float v = acc[mt][nt][cc*2 + p] + bias[gn];
                        int which = gn / CDIM;
                        int rest  = gn - which*CDIM;
                        int h = rest >> 5, d = rest & 31;
                        if (which == 0) v *= SCALE;
                        g_qkv[(((size_t)which*B_WIN + bwi)*NH + h)*(NTOK*HD)
                              + tok*HD + d] = v;
                    }
                }
            }
        }
    } else {
        #pragma unroll
        for (int mt=0; mt<4; mt++){
            #pragma unroll
            for (int cc=0; cc<2; cc++){
                int gm = bm*BM + wm*64 + mt*16 + qt + cc*8;
                #pragma unroll
                for (int nt=0; nt<4; nt++){
                    #pragma unroll
                    for (int p=0; p<2; p++){
                        int gn = bn*BN + wn*32 + nt*8 + 2*qr + p;
                        out[(size_t)gm*N + gn] = acc[mt][nt][cc*2 + p] + bias[gn];
                    }
                }
            }
        }
    }
}

/* ---------------- attention: one CTA per (b, h) ---------------- */
__global__ void __launch_bounds__(128)
attn_kernel(const float* __restrict__ mask, const float* __restrict__ rpb)
{
    __shared__ float qs[64*36], ksm[64*36], vsm[64*36], ps[64*68];

    const int b = blockIdx.y, h = blockIdx.x;
    const int tid = threadIdx.x;
    const int warp = tid >> 5, lane = tid & 31;
    const int qt = lane >> 2, qr = lane & 3;

    const size_t base = ((size_t)b*NH + h)*(NTOK*HD);
    const float* qg = g_qkv + base;                                  /* which=0 */
    const float* kg = g_qkv + (size_t)B_WIN*NH*NTOK*HD   + base;     /* which=1 */
    const float* vg = g_qkv + (size_t)2*B_WIN*NH*NTOK*HD + base;     /* which=2 */

    for (int idx = tid; idx < 64*32; idx += 128){
        int r = idx >> 5, c = idx & 31;
        float q = 0.f, k = 0.f, v = 0.f;
        if (r < NTOK){ q = qg[idx]; k = kg[idx]; v = vg[idx]; }
        qs [r*36 + c] = q;
        ksm[r*36 + c] = k;
        vsm[r*36 + c] = v;
    }
    __syncthreads();

    const int r0 = warp*16 + qt;

    /* S = q @ k^T  (64x64, this warp: rows r0, r0+8 over 16-row slab) */
    float S[8][4];
    #pragma unroll
    for (int nt=0; nt<8; nt++)
        #pragma unroll
        for (int c=0; c<4; c++) S[nt][c] = 0.f;

    #pragma unroll
    for (int kk=0; kk<4; kk++){
        uint32_t a[4];
        a[0] = f2tf32(qs[ r0     *36 + kk*8 + qr    ]);
        a[1] = f2tf32(qs[(r0 + 8)*36 + kk*8 + qr    ]);
        a[2] = f2tf32(qs[ r0     *36 + kk*8 + qr + 4]);
        a[3] = f2tf32(qs[(r0 + 8)*36 + kk*8 + qr + 4]);
        #pragma unroll
        for (int nt=0; nt<8; nt++){
            uint32_t bb[2];
            int m = nt*8 + qt;
            bb[0] = f2tf32(ksm[m*36 + kk*8 + qr    ]);
            bb[1] = f2tf32(ksm[m*36 + kk*8 + qr + 4]);
            mma_tf32(S[nt], a, bb);
        }
    }

    /* + rpb + mask, pad cols>=49 with -1e30 */
    const float* mrow = mask + (size_t)(b & (NWIN-1))*NTOK*NTOK;
    #pragma unroll
    for (int nt=0; nt<8; nt++){
        #pragma unroll
        for (int c=0; c<4; c++){
            int row = r0 + ((c >> 1) << 3);
            int m   = nt*8 + 2*qr + (c & 1);
            if (m >= NTOK){
                S[nt][c] = -1e30f;
            } else if (row < NTOK){
                int ri = row / 7, ci = row - ri*7;
                int rj = m   / 7, cj = m   - rj*7;
                int idx = ((ri - rj + 6)*13 + (ci - cj + 6))*NH + h;
                S[nt][c] += rpb[idx] + mrow[row*NTOK + m];
            }
        }
    }

    /* softmax over m (per-row: spread across 4 lanes qr=0..3) */
    float mx[2] = {-1e30f, -1e30f};
    #pragma unroll
    for (int nt=0; nt<8; nt++)
        #pragma unroll
        for (int c=0; c<4; c++){
            int rs = c >> 1;
            mx[rs] = fmaxf(mx[rs], S[nt][c]);
        }
    #pragma unroll
    for (int o=1; o<4; o<<=1){
        mx[0] = fmaxf(mx[0], __shfl_xor_sync(0xffffffffu, mx[0], o));
        mx[1] = fmaxf(mx[1], __shfl_xor_sync(0xffffffffu, mx[1], o));
    }
    float sm[2] = {0.f, 0.f};
    #pragma unroll
    for (int nt=0; nt<8; nt++)
        #pragma unroll
        for (int c=0; c<4; c++){
            int rs = c >> 1;
            S[nt][c] = __expf(S[nt][c] - mx[rs]);
            sm[rs] += S[nt][c];
        }
    #pragma unroll
    for (int o=1; o<4; o<<=1){
        sm[0] += __shfl_xor_sync(0xffffffffu, sm[0], o);
        sm[1] += __shfl_xor_sync(0xffffffffu, sm[1], o);
    }

    /* P -> smem (per-warp region, warp-local reuse) */
    #pragma unroll
    for (int nt=0; nt<8; nt++){
        #pragma unroll
        for (int c=0; c<4; c++){
            int row = r0 + ((c >> 1) << 3);
            int m   = nt*8 + 2*qr + (c & 1);
            ps[row*68 + m] = S[nt][c];
        }
    }
    __syncwarp();

    /* O = P @ v  (16x32 per warp) */
    float O[4][4];
    #pragma unroll
    for (int nt=0; nt<4; nt++)
        #pragma unroll
        for (int c=0; c<4; c++) O[nt][c] = 0.f;

    #pragma unroll
    for (int ksx=0; ksx<8; ksx++){
        uint32_t a[4];
        a[0] = f2tf32(ps[ r0     *68 + ksx*8 + qr    ]);
        a[1] = f2tf32(ps[(r0 + 8)*68 + ksx*8 + qr    ]);
        a[2] = f2tf32(ps[ r0     *68 + ksx*8 + qr + 4]);
        a[3] = f2tf32(ps[(r0 + 8)*68 + ksx*8 + qr + 4]);
        #pragma unroll
        for (int nt=0; nt<4; nt++){
            uint32_t bb[2];
            bb[0] = f2tf32(vsm[(ksx*8 + qr    )*36 + nt*8 + qt]);
            bb[1] = f2tf32(vsm[(ksx*8 + qr + 4)*36 + nt*8 + qt]);
            mma_tf32(O[nt], a, bb);
        }
    }

    const float inv0 = 1.f / sm[0], inv1 = 1.f / sm[1];
    #pragma unroll
    for (int nt=0; nt<4; nt++){
        #pragma unroll
        for (int c=0; c<4; c++){
            int row = r0 + ((c >> 1) << 3);
            if (row < NTOK){
                int d = nt*8 + 2*qr + (c & 1);
                g_att[((size_t)b*NTOK + row)*CDIM + h*HD + d] =
                    O[nt][c] * ((c >> 1) ? inv1 : inv0);
            }
        }
    }
}

extern "C" void kernel_launch(void* const* d_in, const int* in_sizes, int n_in,
                              void* d_out, int out_size)
{
    const float* x      = (const float*)d_in[0];
    const float* mask   = (const float*)d_in[1];
    const float* qkv_w  = (const float*)d_in[2];
    const float* qkv_b  = (const float*)d_in[3];
    const float* proj_w = (const float*)d_in[4];
    const float* proj_b = (const float*)d_in[5];
    const float* rpb    = (const float*)d_in[6];
    float* out = (float*)d_out;

    const size_t smem_bytes = (size_t)2*(BM + BN)*AST*sizeof(float); /* 73728 */
    cudaFuncSetAttribute(gemm_tn_kernel<0>,
                         cudaFuncAttributeMaxDynamicSharedMemorySize,
                         (int)smem_bytes);
    cudaFuncSetAttribute(gemm_tn_kernel<1>,
                         cudaFuncAttributeMaxDynamicSharedMemorySize,
                         (int)smem_bytes);

    /* K1: qkv = x @ qkv_w^T + b  -> scatter into g_qkv (q pre-scaled) */
    gemm_tn_kernel<1><<<dim3(QKN/BN, MTOT/BM), 256, smem_bytes>>>(
        x, qkv_w, qkv_b, nullptr, QKN, CDIM);

    /* K2: per-(window, head) attention */
    attn_kernel<<<dim3(NH, B_WIN), 128>>>(mask, rpb);

    /* K3: out = attn_out @ proj_w^T + b */
    gemm_tn_kernel<0><<<dim3(CDIM/BN, MTOT/BM), 256, smem_bytes>>>(
        nullptr, proj_w, proj_b, out, CDIM, CDIM);
}